// round 2
// baseline (speedup 1.0000x reference)
#include <cuda_runtime.h>
#include <cstdint>

#define Gs 64
#define Ns 4096
#define Es 256
#define Bs 4
#define KC 32
#define SIGINV 50.0f     // 1 / (2 * 0.1^2)
#define EPSs   1e-8f

// Precomputed separable RBF tables: g_ex[b][gi][n] = exp(-50*(lin[gi]-x_n)^2)
__device__ float g_ex[Bs][Gs][Ns];
__device__ float g_ey[Bs][Gs][Ns];

__global__ void __launch_bounds__(256) table_kernel(const float* __restrict__ pos) {
    int b  = blockIdx.x >> 6;
    int gi = blockIdx.x & 63;
    float gc = (float)gi * (1.0f / 63.0f);
    int t = threadIdx.x;
    const float2* p2 = (const float2*)pos + (size_t)b * Ns;
#pragma unroll
    for (int j = 0; j < Ns / 256; j++) {
        int n = t + j * 256;
        float2 p = p2[n];
        float dx = gc - p.x;
        float dy = gc - p.y;
        g_ex[b][gi][n] = __expf(-SIGINV * dx * dx);
        g_ey[b][gi][n] = __expf(-SIGINV * dy * dy);
    }
}

__device__ __forceinline__ unsigned long long pack_dup(float x) {
    unsigned long long r;
    asm("mov.b64 %0, {%1, %1};" : "=l"(r) : "f"(x));
    return r;
}
__device__ __forceinline__ void ffma2(unsigned long long& d,
                                      unsigned long long a,
                                      unsigned long long b) {
    asm("fma.rn.f32x2 %0, %1, %2, %0;" : "+l"(d) : "l"(a), "l"(b));
}

// One block per (batch, gx). Tile: 64 grid points (gy=0..63) x 256 features.
__global__ void __launch_bounds__(256, 2) grid_kernel(const float* __restrict__ feat,
                                                      float* __restrict__ out) {
    __shared__ float ws[KC * 64];        // weights, transposed [k][p]
    __shared__ float fs[KC * Es];        // feature chunk [k][e]
    __shared__ float sumbuf[64 * 4];

    int b  = blockIdx.x >> 6;
    int gx = blockIdx.x & 63;
    int t  = threadIdx.x;

    // weight-compute mapping: thread -> (pp, k-group of 8)
    int pp = t >> 2;
    int kg = t & 3;
    const float* eyrow = &g_ey[b][pp][0];
    const float* exrow = &g_ex[b][gx][0];

    // MMA mapping: 8x32 thread grid -> 8p x 8e register tile, p packed in pairs
    int r  = t >> 5;
    int c  = t & 31;
    int pb = r * 8;
    int eb = c * 8;

    unsigned long long acc[4][8];        // [p-pair][e], f32x2 accumulators
#pragma unroll
    for (int i = 0; i < 4; i++)
#pragma unroll
        for (int j = 0; j < 8; j++) acc[i][j] = 0ull;
    float psum = 0.0f;

    const float* fbase = feat + (size_t)b * Ns * Es;

    for (int nc = 0; nc < Ns; nc += KC) {
        __syncthreads();   // previous MMA done before overwriting ws/fs

        // Phase A: w[pp][k] = EX[gx][n] * EY[pp][n], transposed store + row sums
#pragma unroll
        for (int jj = 0; jj < 2; jj++) {
            int k0 = kg * 8 + jj * 4;
            float4 ey = *(const float4*)&eyrow[nc + k0];
            float4 ex = *(const float4*)&exrow[nc + k0];
            float w0 = ex.x * ey.x, w1 = ex.y * ey.y;
            float w2 = ex.z * ey.z, w3 = ex.w * ey.w;
            ws[(k0 + 0) * 64 + pp] = w0;
            ws[(k0 + 1) * 64 + pp] = w1;
            ws[(k0 + 2) * 64 + pp] = w2;
            ws[(k0 + 3) * 64 + pp] = w3;
            psum += (w0 + w1) + (w2 + w3);
        }

        // Phase B: stage feature chunk [KC x 256]
        {
            const float4* src = (const float4*)(fbase + (size_t)nc * Es);
            float4* dst = (float4*)fs;
#pragma unroll
            for (int j = 0; j < (KC * Es / 4) / 256; j++)
                dst[t + j * 256] = src[t + j * 256];
        }
        __syncthreads();

        // Phase C: outer-product accumulate, packed f32x2 (pairs along p)
#pragma unroll 4
        for (int k = 0; k < KC; k++) {
            const unsigned long long* wrow =
                (const unsigned long long*)&ws[k * 64 + pb];
            unsigned long long w0 = wrow[0], w1 = wrow[1];
            unsigned long long w2 = wrow[2], w3 = wrow[3];
            float4 fa = *(const float4*)&fs[k * Es + eb];
            float4 fb = *(const float4*)&fs[k * Es + eb + 4];
            unsigned long long fd[8];
            fd[0] = pack_dup(fa.x); fd[1] = pack_dup(fa.y);
            fd[2] = pack_dup(fa.z); fd[3] = pack_dup(fa.w);
            fd[4] = pack_dup(fb.x); fd[5] = pack_dup(fb.y);
            fd[6] = pack_dup(fb.z); fd[7] = pack_dup(fb.w);
#pragma unroll
            for (int e = 0; e < 8; e++) {
                ffma2(acc[0][e], w0, fd[e]);
                ffma2(acc[1][e], w1, fd[e]);
                ffma2(acc[2][e], w2, fd[e]);
                ffma2(acc[3][e], w3, fd[e]);
            }
        }
    }

    __syncthreads();
    sumbuf[pp * 4 + kg] = psum;
    __syncthreads();

    float inv[8];
#pragma unroll
    for (int pi = 0; pi < 8; pi++) {
        int p = pb + pi;
        float s = (sumbuf[p * 4 + 0] + sumbuf[p * 4 + 1]) +
                  (sumbuf[p * 4 + 2] + sumbuf[p * 4 + 3]);
        inv[pi] = 1.0f / (s + EPSs);
    }

    // out[b][e][gx][gy]: contiguous over gy(=p) -> sector-aligned float4 stores
    size_t obase = ((size_t)b * Es) * 4096 + (size_t)gx * 64 + pb;
#pragma unroll
    for (int e = 0; e < 8; e++) {
        float v[8];
#pragma unroll
        for (int pi2 = 0; pi2 < 4; pi2++) {
            float2 f2 = *(float2*)&acc[pi2][e];
            v[2 * pi2 + 0] = f2.x * inv[2 * pi2 + 0];
            v[2 * pi2 + 1] = f2.y * inv[2 * pi2 + 1];
        }
        float* o = out + obase + (size_t)(eb + e) * 4096;
        ((float4*)o)[0] = make_float4(v[0], v[1], v[2], v[3]);
        ((float4*)o)[1] = make_float4(v[4], v[5], v[6], v[7]);
    }
}

extern "C" void kernel_launch(void* const* d_in, const int* in_sizes, int n_in,
                              void* d_out, int out_size) {
    const float* feat = (const float*)d_in[0];  // [4,4096,256] f32
    const float* pos  = (const float*)d_in[1];  // [4,4096,2]   f32
    float* out = (float*)d_out;                 // [4,256,64,64] f32

    table_kernel<<<Bs * Gs, 256>>>(pos);
    grid_kernel<<<Bs * Gs, 256>>>(feat, out);
}

// round 4
// speedup vs baseline: 1.8043x; 1.8043x over previous
#include <cuda_runtime.h>
#include <cstdint>

#define SIGINV 50.0f     // 1 / (2 * 0.1^2)
#define EPSs   1e-8f

// Separable RBF tables (fp32), tf32-rounded transposed features, exact fp32 sums
__device__ float g_ex[4][64][4096];
__device__ float g_ey[4][64][4096];
__device__ float g_ft[4][256][4096];   // Ft[b][e][n] = rna_tf32(F[b][n][e])
__device__ float g_sumw[4][4096];

// ---------------- helpers ----------------
__device__ __forceinline__ uint32_t smem_u32(const void* p) {
    uint32_t a;
    asm("{ .reg .u64 t; cvta.to.shared.u64 t, %1; cvt.u32.u64 %0, t; }"
        : "=r"(a) : "l"(p));
    return a;
}
__device__ __forceinline__ uint32_t f2tf32(float x) {
    uint32_t r;
    asm("cvt.rna.tf32.f32 %0, %1;" : "=r"(r) : "f"(x));
    return r;
}
__device__ __forceinline__ uint32_t lds32(uint32_t a) {
    uint32_t v;
    asm volatile("ld.shared.b32 %0, [%1];" : "=r"(v) : "r"(a));
    return v;
}

// ---------------- pre-kernels ----------------
__global__ void __launch_bounds__(256) table_kernel(const float* __restrict__ pos) {
    int b = blockIdx.x >> 6, gi = blockIdx.x & 63;
    float gc = (float)gi * (1.0f / 63.0f);
    int t = threadIdx.x;
    const float2* p2 = (const float2*)pos + (size_t)b * 4096;
#pragma unroll
    for (int j = 0; j < 16; j++) {
        int n = t + j * 256;
        float2 p = p2[n];
        float dx = gc - p.x, dy = gc - p.y;
        g_ex[b][gi][n] = __expf(-SIGINV * dx * dx);
        g_ey[b][gi][n] = __expf(-SIGINV * dy * dy);
    }
}

__global__ void __launch_bounds__(256) transpose_kernel(const float* __restrict__ feat) {
    __shared__ float tile[32][33];
    int b = blockIdx.z, n0 = blockIdx.x * 32, e0 = blockIdx.y * 32;
    int tx = threadIdx.x & 31, ty = threadIdx.x >> 5;
    const float* src = feat + ((size_t)b * 4096 + n0) * 256 + e0;
#pragma unroll
    for (int j = 0; j < 4; j++)
        tile[ty + j * 8][tx] = src[(size_t)(ty + j * 8) * 256 + tx];
    __syncthreads();
    float* dst = &g_ft[b][e0][n0];
#pragma unroll
    for (int j = 0; j < 4; j++)
        dst[(size_t)(ty + j * 8) * 4096 + tx] =
            __uint_as_float(f2tf32(tile[tx][ty + j * 8]));
}

__global__ void __launch_bounds__(256) sum_kernel() {
    __shared__ float red[256];
    int b = blockIdx.x >> 6, gx = blockIdx.x & 63;
    int t = threadIdx.x, gy = t >> 2, q = t & 3;
    const float4* ex = (const float4*)&g_ex[b][gx][q * 1024];
    const float4* ey = (const float4*)&g_ey[b][gy][q * 1024];
    float s = 0.0f;
#pragma unroll 4
    for (int i = 0; i < 256; i++) {
        float4 a = ex[i], c = ey[i];
        s += a.x * c.x + a.y * c.y + a.z * c.z + a.w * c.w;
    }
    red[t] = s;
    __syncthreads();
    if (q == 0)
        g_sumw[b][gx * 64 + gy] = (red[t] + red[t + 1]) + (red[t + 2] + red[t + 3]);
}

// ---------------- main mma.sync tf32 kernel ----------------
// block = (b, mt): D[128p x 256e] = W[128 x 4096] * Ft^T, K chunks of 32.
// smem per stage: ws[128][36] (18432 B) + fs[256][36] (36864 B) = 55296 B, x2 buffers.
#define WSB   18432
#define STAGE 55296
#define SMEMT (2 * STAGE)   // 110592

__global__ void __launch_bounds__(256, 1) mma_kernel(float* __restrict__ out) {
    extern __shared__ char smem[];
    uint32_t sb = smem_u32(smem);
    const int t = threadIdx.x, w = t >> 5, l = t & 31;
    const int blk = blockIdx.x, b = blk >> 5, mt = blk & 31;

    // --- staging maps ---
    const int sr = t >> 1, kseg = (t & 1) * 16;           // ws row / 16-wide k half
    const float* exrow = &g_ex[b][mt * 2 + (sr >> 6)][0];
    const float* eyrow = &g_ey[b][sr & 63][0];
    const uint32_t wsAddr = sb + sr * 144 + kseg * 4;
    const float* ftrow = &g_ft[b][t][0];                  // fs row e = t
    const uint32_t fsAddr = sb + WSB + t * 144;

    // --- mma fragment maps ---
    const int wm = w & 1, wn = w >> 1, g = l >> 2, tig = l & 3;
    const uint32_t aBase = sb + (wm * 64 + g) * 144 + tig * 4;
    const uint32_t bBase = sb + WSB + (wn * 64 + g) * 144 + tig * 4;

    float acc[4][8][4];
#pragma unroll
    for (int i = 0; i < 4; i++)
#pragma unroll
        for (int j = 0; j < 8; j++)
#pragma unroll
            for (int q = 0; q < 4; q++) acc[i][j][q] = 0.0f;

#define STAGE_CHUNK(c, s)                                                     \
    do {                                                                      \
        const uint32_t so = (s) * STAGE;                                      \
        const int nc = (c) * 32;                                              \
        const float* fsrc = ftrow + nc;                                       \
        _Pragma("unroll")                                                     \
        for (int j = 0; j < 8; j++)                                           \
            asm volatile("cp.async.cg.shared.global [%0], [%1], 16;"          \
                         :: "r"(fsAddr + so + 16 * j), "l"(fsrc + 4 * j)      \
                         : "memory");                                         \
        asm volatile("cp.async.commit_group;" ::: "memory");                  \
        _Pragma("unroll")                                                     \
        for (int q = 0; q < 4; q++) {                                         \
            float4 ex = *(const float4*)(exrow + nc + kseg + 4 * q);          \
            float4 ey = *(const float4*)(eyrow + nc + kseg + 4 * q);          \
            uint32_t w0 = f2tf32(ex.x * ey.x), w1 = f2tf32(ex.y * ey.y);      \
            uint32_t w2 = f2tf32(ex.z * ey.z), w3 = f2tf32(ex.w * ey.w);      \
            asm volatile("st.shared.v4.b32 [%0], {%1,%2,%3,%4};"              \
                         :: "r"(wsAddr + so + 16 * q),                        \
                            "r"(w0), "r"(w1), "r"(w2), "r"(w3) : "memory");   \
        }                                                                     \
    } while (0)

    STAGE_CHUNK(0, 0);

    for (int c = 0; c < 128; c++) {
        const int s = c & 1;
        if (c < 127) {
            STAGE_CHUNK(c + 1, s ^ 1);
            asm volatile("cp.async.wait_group 1;" ::: "memory");
        } else {
            asm volatile("cp.async.wait_group 0;" ::: "memory");
        }
        __syncthreads();

        const uint32_t so = s * STAGE;
#pragma unroll
        for (int kt = 0; kt < 4; kt++) {
            uint32_t a[4][4];
#pragma unroll
            for (int i = 0; i < 4; i++) {
                uint32_t ad = aBase + so + i * 2304 + kt * 32;
                a[i][0] = lds32(ad);
                a[i][1] = lds32(ad + 1152);
                a[i][2] = lds32(ad + 16);
                a[i][3] = lds32(ad + 1152 + 16);
            }
#pragma unroll
            for (int jn = 0; jn < 8; jn++) {
                uint32_t bd = bBase + so + jn * 1152 + kt * 32;
                uint32_t b0 = lds32(bd), b1 = lds32(bd + 16);
#pragma unroll
                for (int i = 0; i < 4; i++) {
                    float* d = acc[i][jn];
                    asm volatile(
                        "mma.sync.aligned.m16n8k8.row.col.f32.tf32.tf32.f32 "
                        "{%0,%1,%2,%3}, {%4,%5,%6,%7}, {%8,%9}, {%0,%1,%2,%3};"
                        : "+f"(d[0]), "+f"(d[1]), "+f"(d[2]), "+f"(d[3])
                        : "r"(a[i][0]), "r"(a[i][1]), "r"(a[i][2]), "r"(a[i][3]),
                          "r"(b0), "r"(b1));
                }
            }
        }
        __syncthreads();
    }

    // --- epilogue: normalize by exact fp32 sums, scatter to [b][e][gx][gy] ---
    const size_t obase = (size_t)b * 256 * 4096;
#pragma unroll
    for (int i = 0; i < 4; i++) {
        int p0 = mt * 128 + wm * 64 + i * 16 + g;
        int p1 = p0 + 8;
        float inv0 = 1.0f / (g_sumw[b][p0] + EPSs);
        float inv1 = 1.0f / (g_sumw[b][p1] + EPSs);
#pragma unroll
        for (int jn = 0; jn < 8; jn++) {
            int e0 = wn * 64 + jn * 8 + tig * 2;
            float* o0 = out + obase + (size_t)e0 * 4096;
            float* o1 = o0 + 4096;
            o0[p0] = acc[i][jn][0] * inv0;
            o1[p0] = acc[i][jn][1] * inv0;
            o0[p1] = acc[i][jn][2] * inv1;
            o1[p1] = acc[i][jn][3] * inv1;
        }
    }
}

extern "C" void kernel_launch(void* const* d_in, const int* in_sizes, int n_in,
                              void* d_out, int out_size) {
    const float* feat = (const float*)d_in[0];  // [4,4096,256]
    const float* pos  = (const float*)d_in[1];  // [4,4096,2]
    float* out = (float*)d_out;                 // [4,256,64,64]

    cudaFuncSetAttribute(mma_kernel,
                         cudaFuncAttributeMaxDynamicSharedMemorySize, SMEMT);

    table_kernel<<<256, 256>>>(pos);
    transpose_kernel<<<dim3(128, 8, 4), 256>>>(feat);
    sum_kernel<<<256, 256>>>();
    mma_kernel<<<128, 256, SMEMT>>>(out);
}